// round 11
// baseline (speedup 1.0000x reference)
#include <cuda_runtime.h>
#include <math.h>
#include <stdint.h>

#define Bz   64
#define Tt   512
#define Fin  128
#define Un   1024
#define G4   4096
#define NCLS 16
#define KC   32
#define GRID 128

// persistent state
__device__ float g_h0[2][Bz*Un];
__device__ float g_c0[Bz*Un];
__device__ float g_h1[2][Bz*Un];
__device__ float g_c1[Bz*Un];
__device__ __align__(16) float2 g_part0[Bz*GRID];
__device__ __align__(16) float2 g_part1[Bz*GRID];
__device__ unsigned g_count;
__device__ unsigned g_gen;

union U64F2 { unsigned long long u; float2 f; };

__device__ __forceinline__ float sigm(float x){ return 1.f/(1.f+expf(-x)); }

// grid-wide sense barrier (all 128 blocks resident => safe)
__device__ __forceinline__ void gridbar(unsigned &gen){
    __syncthreads();
    if (threadIdx.x == 0){
        __threadfence();
        unsigned arr = atomicAdd(&g_count, 1u);
        if (arr == (unsigned)(gridDim.x - 1)){
            g_count = 0u;
            __threadfence();
            atomicExch(&g_gen, gen + 1u);
        } else {
            unsigned cur;
            do {
                asm volatile("ld.acquire.gpu.global.u32 %0, [%1];" : "=r"(cur) : "l"(&g_gen));
            } while (cur == gen);
        }
    }
    gen++;
    __syncthreads();
}

// one K-chunk: per thread 2 rows x 4 cols, packed f32x2 FMAs
// sA: [KC][66] natural rows (64 + pad2). sU: [KC][32] natural cols.
__device__ __forceinline__ void compute_chunk(
    const float* __restrict__ sA, const float* __restrict__ sU,
    int pg, int cg, unsigned long long acc[4])
{
    const float* pa = sA + 2*pg;
    const float* pu = sU + 4*cg;
#pragma unroll
    for (int k = 0; k < KC; k++){
        float2 av = *reinterpret_cast<const float2*>(pa + k*66);
        ulonglong2 uv = *reinterpret_cast<const ulonglong2*>(pu + k*32);
        unsigned long long d0, d1;
        asm("mov.b64 %0,{%1,%1};" : "=l"(d0) : "f"(av.x));
        asm("mov.b64 %0,{%1,%1};" : "=l"(d1) : "f"(av.y));
        asm("fma.rn.f32x2 %0,%1,%2,%0;" : "+l"(acc[0]) : "l"(d0), "l"(uv.x));
        asm("fma.rn.f32x2 %0,%1,%2,%0;" : "+l"(acc[1]) : "l"(d0), "l"(uv.y));
        asm("fma.rn.f32x2 %0,%1,%2,%0;" : "+l"(acc[2]) : "l"(d1), "l"(uv.x));
        asm("fma.rn.f32x2 %0,%1,%2,%0;" : "+l"(acc[3]) : "l"(d1), "l"(uv.y));
    }
}

__global__ void initState(){
    int i = blockIdx.x*blockDim.x + threadIdx.x;
    if (i == 0){ g_count = 0u; g_gen = 0u; }
    int stride = gridDim.x*blockDim.x;
    for (int j = i; j < Bz*Un; j += stride){
        g_h0[0][j]=0.f; g_h0[1][j]=0.f; g_c0[j]=0.f;
        g_h1[0][j]=0.f; g_h1[1][j]=0.f; g_c1[j]=0.f;
    }
}

__global__ void __launch_bounds__(256,1) lstm_persistent(
    const float* __restrict__ x,
    const float* __restrict__ W0, const float* __restrict__ U0, const float* __restrict__ b0,
    const float* __restrict__ g0, const float* __restrict__ be0,
    const float* __restrict__ W1, const float* __restrict__ U1, const float* __restrict__ b1,
    const float* __restrict__ g1, const float* __restrict__ be1,
    const float* __restrict__ Wfc, const float* __restrict__ bfc,
    float* __restrict__ out)
{
    __shared__ __align__(16) float sPool[6272];   // sA0|sA1|sU0|sU1 ; aliased by sZ / sO
    __shared__ float s_mu[64], s_rs[64];
    __shared__ float s_logit[16];
    __shared__ float s_st[2];

    float* sA0 = sPool;                 // 2112 floats (32*66)
    float* sA1 = sPool + 2112;
    float* sU0 = sPool + 4224;          // 1024 floats (32*32)
    float* sU1 = sPool + 5248;
    float* sZ  = sPool;                 // epilogue alias (64*34 = 2176 floats)
    float* sO  = sPool;                 // phase-C alias (1024 floats)

    const int tid  = threadIdx.x;
    const int b    = blockIdx.x;
    const int u0   = b * 8;
    const int cg   = tid & 7;           // 4 cols: 4cg..4cg+3
    const int pg   = tid >> 3;          // 2 rows: 2pg, 2pg+1
    const int lane = tid & 31, warp = tid >> 5;

    // staging maps
    const int kA  = tid & 31;           // A: lane varies k
    const int rA0 = tid >> 5;           // rows rA0 + 8p (p<8)
    const int cS  = tid & 31;           // U: lane varies col
    const int kU0 = tid >> 5;           // rows kU0 + 8p (p<4)
    const int gcS = ((cS >> 3) << 10) + u0 + (cS & 7);

    const int ci0 = 4*cg;
    const int gc  = ((ci0 >> 3) << 10) + u0 + (ci0 & 7);   // contiguous 4 cols
    float bias0[4], bias1[4];
#pragma unroll
    for (int j=0;j<4;j++){ bias0[j] = __ldg(b0 + gc + j); bias1[j] = __ldg(b1 + gc + j); }

    unsigned gen = 0;
    float rAr[8], rUr[4];

#pragma unroll 1
    for (int t = 0; t < Tt; t++){
        const int ping = t & 1;
        const float* h0_in  = g_h0[ping];
        float*       h0_out = g_h0[ping^1];
        const float* h1_in  = g_h1[ping];
        float*       h1_out = g_h1[ping^1];

        // ============== phase A : layer-0 GEMM + gates ==============
        {
            unsigned long long acc[4];
            { U64F2 v; v.f = make_float2(bias0[0], bias0[1]); acc[0]=v.u;
                       v.f = make_float2(bias0[2], bias0[3]); acc[1]=v.u;
              acc[2]=acc[0]; acc[3]=acc[1]; }

            auto ldgA = [&](int cc){
                if (cc < 32){
                    int k = cc*KC + kA;
#pragma unroll
                    for (int p=0;p<8;p++) rAr[p] = __ldcg(h0_in + (rA0+8*p)*Un + k);
                    const float* ub = U0 + (size_t)(cc*KC)*G4 + gcS;
#pragma unroll
                    for (int p=0;p<4;p++) rUr[p] = __ldg(ub + (size_t)(kU0+8*p)*G4);
                } else {
                    int j = cc - 32;
                    int k = j*KC + kA;
#pragma unroll
                    for (int p=0;p<8;p++) rAr[p] = __ldg(x + ((size_t)(rA0+8*p)*Tt + t)*Fin + k);
                    const float* ub = W0 + (size_t)(j*KC)*G4 + gcS;
#pragma unroll
                    for (int p=0;p<4;p++) rUr[p] = __ldg(ub + (size_t)(kU0+8*p)*G4);
                }
            };
            auto stsA = [&](float* sa, float* su){
#pragma unroll
                for (int p=0;p<8;p++) sa[kA*66 + rA0 + 8*p] = rAr[p];
#pragma unroll
                for (int p=0;p<4;p++) su[(kU0+8*p)*32 + cS] = rUr[p];
            };

            ldgA(0); stsA(sA0, sU0);
            __syncthreads();
#pragma unroll 1
            for (int cc=0; cc<36; cc++){
                const float* ca = (cc&1)? sA1 : sA0;
                const float* cu = (cc&1)? sU1 : sU0;
                if (cc+1 < 36) ldgA(cc+1);
                compute_chunk(ca, cu, pg, cg, acc);
                if (cc+1 < 36) stsA((cc&1)? sA0:sA1, (cc&1)? sU0:sU1);
                __syncthreads();
            }
            {
                U64F2 v; int r0 = 2*pg;
                v.u=acc[0]; *reinterpret_cast<float2*>(sZ + r0*34 + ci0)       = v.f;
                v.u=acc[1]; *reinterpret_cast<float2*>(sZ + r0*34 + ci0 + 2)   = v.f;
                v.u=acc[2]; *reinterpret_cast<float2*>(sZ + (r0+1)*34 + ci0)   = v.f;
                v.u=acc[3]; *reinterpret_cast<float2*>(sZ + (r0+1)*34 + ci0+2) = v.f;
            }
            __syncthreads();
#pragma unroll
            for (int it=0; it<2; it++){
                int idx = tid + it*256;
                int r = idx >> 3, uu = idx & 7;
                float zi = sZ[r*34 + uu];
                float zf = sZ[r*34 + 8 + uu];
                float zg = sZ[r*34 + 16 + uu];
                float zo = sZ[r*34 + 24 + uu];
                float gi = sigm(zi), gf = sigm(zf), gg = tanhf(zg), go = sigm(zo);
                int gidx = r*Un + u0 + uu;
                float cn = gf * g_c0[gidx] + gi*gg;
                g_c0[gidx] = cn;
                float h = go * tanhf(cn);
                __stcg(h0_out + gidx, h);
                float s = h, q = h*h;
                s += __shfl_down_sync(0xffffffffu, s, 4, 8);
                q += __shfl_down_sync(0xffffffffu, q, 4, 8);
                s += __shfl_down_sync(0xffffffffu, s, 2, 8);
                q += __shfl_down_sync(0xffffffffu, q, 2, 8);
                s += __shfl_down_sync(0xffffffffu, s, 1, 8);
                q += __shfl_down_sync(0xffffffffu, q, 1, 8);
                if ((tid & 7) == 0)
                    __stcg(&g_part0[r*GRID + b], make_float2(s, q));
            }
        }
        gridbar(gen);

        // ============== phase B : LN(h0) + layer-1 GEMM + gates ==============
        {
            // reduce layer-0 LN partials -> s_mu/s_rs (warp w owns rows 8w..8w+7)
#pragma unroll
            for (int rr=0; rr<8; rr++){
                int r = warp*8 + rr;
                const float4* p = reinterpret_cast<const float4*>(g_part0 + r*GRID);
                float4 A  = __ldcg(p + lane*2);
                float4 Bv = __ldcg(p + lane*2 + 1);
                float s = A.x + A.z + Bv.x + Bv.z;
                float q = A.y + A.w + Bv.y + Bv.w;
#pragma unroll
                for (int o=16;o;o>>=1){
                    s += __shfl_down_sync(0xffffffffu, s, o);
                    q += __shfl_down_sync(0xffffffffu, q, o);
                }
                if (lane == 0){
                    float mu  = s * (1.f/1024.f);
                    float var = fmaxf(q * (1.f/1024.f) - mu*mu, 0.f);
                    s_mu[r] = mu; s_rs[r] = rsqrtf(var + 1e-3f);
                }
            }
            __syncthreads();

            unsigned long long acc[4];
            { U64F2 v; v.f = make_float2(bias1[0], bias1[1]); acc[0]=v.u;
                       v.f = make_float2(bias1[2], bias1[3]); acc[1]=v.u;
              acc[2]=acc[0]; acc[3]=acc[1]; }

            float gk = 0.f, bek = 0.f;
            auto ldgB = [&](int cc){
                if (cc < 32){
                    int k = cc*KC + kA;
#pragma unroll
                    for (int p=0;p<8;p++) rAr[p] = __ldcg(h1_in + (rA0+8*p)*Un + k);
                    const float* ub = U1 + (size_t)(cc*KC)*G4 + gcS;
#pragma unroll
                    for (int p=0;p<4;p++) rUr[p] = __ldg(ub + (size_t)(kU0+8*p)*G4);
                } else {
                    int j = cc - 32;
                    int k = j*KC + kA;
                    gk = __ldg(g0 + k); bek = __ldg(be0 + k);
#pragma unroll
                    for (int p=0;p<8;p++) rAr[p] = __ldcg(h0_out + (rA0+8*p)*Un + k);
                    const float* ub = W1 + (size_t)(j*KC)*G4 + gcS;
#pragma unroll
                    for (int p=0;p<4;p++) rUr[p] = __ldg(ub + (size_t)(kU0+8*p)*G4);
                }
            };
            auto stsB = [&](float* sa, float* su, bool norm){
                if (norm){
#pragma unroll
                    for (int p=0;p<8;p++){
                        int r = rA0 + 8*p;
                        sa[kA*66 + r] = (rAr[p] - s_mu[r]) * s_rs[r] * gk + bek;
                    }
                } else {
#pragma unroll
                    for (int p=0;p<8;p++) sa[kA*66 + rA0 + 8*p] = rAr[p];
                }
#pragma unroll
                for (int p=0;p<4;p++) su[(kU0+8*p)*32 + cS] = rUr[p];
            };

            ldgB(0); stsB(sA0, sU0, false);
            __syncthreads();
#pragma unroll 1
            for (int cc=0; cc<64; cc++){
                const float* ca = (cc&1)? sA1 : sA0;
                const float* cu = (cc&1)? sU1 : sU0;
                if (cc+1 < 64) ldgB(cc+1);
                compute_chunk(ca, cu, pg, cg, acc);
                if (cc+1 < 64) stsB((cc&1)? sA0:sA1, (cc&1)? sU0:sU1, (cc+1) >= 32);
                __syncthreads();
            }
            {
                U64F2 v; int r0 = 2*pg;
                v.u=acc[0]; *reinterpret_cast<float2*>(sZ + r0*34 + ci0)       = v.f;
                v.u=acc[1]; *reinterpret_cast<float2*>(sZ + r0*34 + ci0 + 2)   = v.f;
                v.u=acc[2]; *reinterpret_cast<float2*>(sZ + (r0+1)*34 + ci0)   = v.f;
                v.u=acc[3]; *reinterpret_cast<float2*>(sZ + (r0+1)*34 + ci0+2) = v.f;
            }
            __syncthreads();
#pragma unroll
            for (int it=0; it<2; it++){
                int idx = tid + it*256;
                int r = idx >> 3, uu = idx & 7;
                float zi = sZ[r*34 + uu];
                float zf = sZ[r*34 + 8 + uu];
                float zg = sZ[r*34 + 16 + uu];
                float zo = sZ[r*34 + 24 + uu];
                float gi = sigm(zi), gf = sigm(zf), gg = tanhf(zg), go = sigm(zo);
                int gidx = r*Un + u0 + uu;
                float cn = gf * g_c1[gidx] + gi*gg;
                g_c1[gidx] = cn;
                float h = go * tanhf(cn);
                __stcg(h1_out + gidx, h);
                float s = h, q = h*h;
                s += __shfl_down_sync(0xffffffffu, s, 4, 8);
                q += __shfl_down_sync(0xffffffffu, q, 4, 8);
                s += __shfl_down_sync(0xffffffffu, s, 2, 8);
                q += __shfl_down_sync(0xffffffffu, q, 2, 8);
                s += __shfl_down_sync(0xffffffffu, s, 1, 8);
                q += __shfl_down_sync(0xffffffffu, q, 1, 8);
                if ((tid & 7) == 0)
                    __stcg(&g_part1[r*GRID + b], make_float2(s, q));
            }
        }
        gridbar(gen);

        // ============== phase C : LN(h1) + FC + softmax (blocks 0..63) ==============
        if (b < 64){
            const float* h = h1_out + b*Un;
            float v[4];
#pragma unroll
            for (int i=0;i<4;i++) v[i] = __ldcg(h + tid + i*256);
            if (warp == 0){
                const float4* p = reinterpret_cast<const float4*>(g_part1 + b*GRID);
                float4 A  = __ldcg(p + lane*2);
                float4 Bv = __ldcg(p + lane*2 + 1);
                float s = A.x + A.z + Bv.x + Bv.z;
                float q = A.y + A.w + Bv.y + Bv.w;
#pragma unroll
                for (int o=16;o;o>>=1){
                    s += __shfl_down_sync(0xffffffffu, s, o);
                    q += __shfl_down_sync(0xffffffffu, q, o);
                }
                if (lane == 0){
                    float mu  = s * (1.f/1024.f);
                    float var = fmaxf(q * (1.f/1024.f) - mu*mu, 0.f);
                    s_st[0] = mu; s_st[1] = rsqrtf(var + 1e-3f);
                }
            }
            __syncthreads();
            float mu = s_st[0], rs = s_st[1];
#pragma unroll
            for (int i=0;i<4;i++){
                int k = tid + i*256;
                sO[k] = (v[i]-mu)*rs*__ldg(g1+k) + __ldg(be1+k);
            }
            __syncthreads();
            {
                float l0 = 0.f, l1 = 0.f;
#pragma unroll 4
                for (int k=lane; k<Un; k+=32){
                    float o = sO[k];
                    l0 += o * __ldg(Wfc + k*NCLS + 2*warp);
                    l1 += o * __ldg(Wfc + k*NCLS + 2*warp + 1);
                }
#pragma unroll
                for (int o=16;o;o>>=1){
                    l0 += __shfl_down_sync(0xffffffffu, l0, o);
                    l1 += __shfl_down_sync(0xffffffffu, l1, o);
                }
                if (lane == 0){
                    s_logit[2*warp]   = l0 + __ldg(bfc + 2*warp);
                    s_logit[2*warp+1] = l1 + __ldg(bfc + 2*warp+1);
                }
            }
            __syncthreads();
            if (tid < NCLS){
                float m = -1e30f;
#pragma unroll
                for (int j=0;j<NCLS;j++) m = fmaxf(m, s_logit[j]);
                float ss = 0.f;
#pragma unroll
                for (int j=0;j<NCLS;j++) ss += expf(s_logit[j]-m);
                out[((size_t)b*Tt + t)*NCLS + tid] = expf(s_logit[tid]-m) / ss;
            }
            __syncthreads();   // protect sO before next-t staging reuses sPool
        }
    }
}

extern "C" void kernel_launch(void* const* d_in, const int* in_sizes, int n_in,
                              void* d_out, int out_size)
{
    const float* x   = (const float*)d_in[0];
    const float* W0  = (const float*)d_in[1];
    const float* U0  = (const float*)d_in[2];
    const float* b0  = (const float*)d_in[3];
    const float* g0  = (const float*)d_in[4];
    const float* be0 = (const float*)d_in[5];
    const float* W1  = (const float*)d_in[6];
    const float* U1  = (const float*)d_in[7];
    const float* b1  = (const float*)d_in[8];
    const float* g1  = (const float*)d_in[9];
    const float* be1 = (const float*)d_in[10];
    const float* Wfc = (const float*)d_in[11];
    const float* bfc = (const float*)d_in[12];
    float* out = (float*)d_out;

    initState<<<128, 512>>>();
    lstm_persistent<<<GRID, 256>>>(x, W0, U0, b0, g0, be0,
                                   W1, U1, b1, g1, be1, Wfc, bfc, out);
}